// round 15
// baseline (speedup 1.0000x reference)
#include <cuda_runtime.h>
#include <cstdint>
#include <math.h>

#define BB 64
#define HH 256
#define WW 256
#define HWSZ 65536
#define NTOT 4194304

#define OFF_UIFFT 0
#define OFF_ABS   8388608
#define OFF_MASK  12582912
#define OFF_FFT   16777216
#define OFF_UK    25165824

__device__ double g_partial[64];
__device__ float  g_r, g_beta;
__device__ int    g_le;
__device__ float  g_prob2[HWSZ];   // holds prob1 (pre-rescale)
__device__ float g_t1r_f[256], g_t1i_f[256], g_t1r_i[256], g_t1i_i[256];
__device__ float g_t2r_f[256], g_t2i_f[256], g_t2r_i[256], g_t2i_i[256];

// ---------------- Threefry-2x32-20 (exact jax) ----------------
__host__ __device__ __forceinline__ unsigned rotl32(unsigned v, int d) {
    return (v << d) | (v >> (32 - d));
}

__host__ __device__ __forceinline__ void threefry2x32(unsigned k0, unsigned k1,
                                                      unsigned c0, unsigned c1,
                                                      unsigned& o0, unsigned& o1) {
    unsigned ks2 = k0 ^ k1 ^ 0x1BD11BDAu;
    unsigned x0 = c0 + k0;
    unsigned x1 = c1 + k1;
#define TF_R(r) { x0 += x1; x1 = rotl32(x1, r); x1 ^= x0; }
    TF_R(13) TF_R(15) TF_R(26) TF_R(6)
    x0 += k1;  x1 += ks2 + 1u;
    TF_R(17) TF_R(29) TF_R(16) TF_R(24)
    x0 += ks2; x1 += k0 + 2u;
    TF_R(13) TF_R(15) TF_R(26) TF_R(6)
    x0 += k0;  x1 += k1 + 3u;
    TF_R(17) TF_R(29) TF_R(16) TF_R(24)
    x0 += k1;  x1 += ks2 + 4u;
    TF_R(13) TF_R(15) TF_R(26) TF_R(6)
    x0 += ks2; x1 += k0 + 5u;
#undef TF_R
    o0 = x0; o1 = x1;
}

// ---------------- XLA-exact sigmoid pieces ----------------
__device__ __forceinline__ float tanh_xla(float x) {
    float ax = fabsf(x);
    float xc = fminf(fmaxf(x, -7.90531110763549805f), 7.90531110763549805f);
    float x2 = __fmul_rn(xc, xc);
    float p = -2.76076847742355e-16f;
    p = fmaf(p, x2, 2.00018790482477e-13f);
    p = fmaf(p, x2, -8.60467152213735e-11f);
    p = fmaf(p, x2, 5.12229709037114e-08f);
    p = fmaf(p, x2, 1.48572235717979e-05f);
    p = fmaf(p, x2, 6.37261928875436e-04f);
    p = fmaf(p, x2, 4.89352455891786e-03f);
    p = __fmul_rn(p, xc);
    float q = 1.19825839466702e-06f;
    q = fmaf(q, x2, 1.18534705686654e-04f);
    q = fmaf(q, x2, 2.26843463243900e-03f);
    q = fmaf(q, x2, 4.89352518554385e-03f);
    float r = __fdiv_rn(p, q);
    return (ax < 0.0004f) ? x : r;
}

__device__ __forceinline__ float prob1_of(float wv) {
    float arg = __fmul_rn(0.5f, __fmul_rn(5.0f, wv));
    float t = tanh_xla(arg);
    return __fadd_rn(0.5f, __fmul_rn(0.5f, t));
}

// ---------------- reduction: prob1 -> g_prob2, partial sums ----------------
__global__ void k_reduce(const float* __restrict__ w) {
    __shared__ double sd[256];
    int t = threadIdx.x;
    int i0 = (blockIdx.x * 256 + t) * 4;
    float4 wq = *reinterpret_cast<const float4*>(w + i0);
    float p0 = prob1_of(wq.x), p1 = prob1_of(wq.y);
    float p2 = prob1_of(wq.z), p3 = prob1_of(wq.w);
    *reinterpret_cast<float4*>(g_prob2 + i0) = make_float4(p0, p1, p2, p3);
    sd[t] = (double)p0 + (double)p1 + (double)p2 + (double)p3;
    __syncthreads();
    for (int s = 128; s > 0; s >>= 1) {
        if (t < s) sd[t] += sd[t + s];
        __syncthreads();
    }
    if (t == 0) g_partial[blockIdx.x] = sd[0];
}

// final sum + constants + four-step twiddle tables
__global__ void k_final() {
    __shared__ double sd[64];
    int t = threadIdx.x;
    if (t < 64) sd[t] = g_partial[t];
    {
        int c = t >> 5, l = t & 31;
        float s1, c1;
        sincospif((float)(l * c) / 128.0f, &s1, &c1);
        g_t1r_f[t] = c1; g_t1i_f[t] = -s1;
        g_t1r_i[t] = c1; g_t1i_i[t] = s1;
        int d0 = ((l >> 4) & 1) + (((l >> 3) & 1) << 1);
        float s2, c2;
        sincospif((float)(c * d0) / 16.0f, &s2, &c2);
        g_t2r_f[t] = c2; g_t2i_f[t] = -s2;
        const float sc = 1.0f / 256.0f;
        g_t2r_i[t] = c2 * sc; g_t2i_i[t] = s2 * sc;
    }
    __syncthreads();
    for (int s = 32; s > 0; s >>= 1) {
        if (t < s) sd[t] += sd[t + s];
        __syncthreads();
    }
    if (t == 0) {
        float xbar = (float)(sd[0] / 65536.0);
        g_r    = __fdiv_rn(0.125f, xbar);
        g_beta = __fdiv_rn(0.875f, __fsub_rn(1.0f, xbar));
        g_le   = (g_r < 1.0f) ? 1 : 0;
    }
}

// ---------------- four-step register FFT pieces ----------------
#define SWZ(row) ((row) ^ ((row) >> 5))
#define HSQ 0.70710678118654752f

template<int SIGN>
__device__ __forceinline__ void radix8(float (&vr)[8], float (&vi)[8]) {
    const float E = (float)SIGN;
    float tr, ti;
    tr=vr[0]-vr[4]; ti=vi[0]-vi[4]; vr[0]+=vr[4]; vi[0]+=vi[4]; vr[4]=tr; vi[4]=ti;
    tr=vr[1]-vr[5]; ti=vi[1]-vi[5]; vr[1]+=vr[5]; vi[1]+=vi[5];
    vr[5]=HSQ*(tr - E*ti); vi[5]=HSQ*(ti + E*tr);
    tr=vr[2]-vr[6]; ti=vi[2]-vi[6]; vr[2]+=vr[6]; vi[2]+=vi[6];
    vr[6]=-E*ti; vi[6]=E*tr;
    tr=vr[3]-vr[7]; ti=vi[3]-vi[7]; vr[3]+=vr[7]; vi[3]+=vi[7];
    vr[7]=-HSQ*(tr + E*ti); vi[7]=HSQ*(E*tr - ti);
    tr=vr[0]-vr[2]; ti=vi[0]-vi[2]; vr[0]+=vr[2]; vi[0]+=vi[2]; vr[2]=tr; vi[2]=ti;
    tr=vr[1]-vr[3]; ti=vi[1]-vi[3]; vr[1]+=vr[3]; vi[1]+=vi[3]; vr[3]=-E*ti; vi[3]=E*tr;
    tr=vr[4]-vr[6]; ti=vi[4]-vi[6]; vr[4]+=vr[6]; vi[4]+=vi[6]; vr[6]=tr; vi[6]=ti;
    tr=vr[5]-vr[7]; ti=vi[5]-vi[7]; vr[5]+=vr[7]; vi[5]+=vi[7]; vr[7]=-E*ti; vi[7]=E*tr;
    tr=vr[0]-vr[1]; ti=vi[0]-vi[1]; vr[0]+=vr[1]; vi[0]+=vi[1]; vr[1]=tr; vi[1]=ti;
    tr=vr[2]-vr[3]; ti=vi[2]-vi[3]; vr[2]+=vr[3]; vi[2]+=vi[3]; vr[3]=tr; vi[3]=ti;
    tr=vr[4]-vr[5]; ti=vi[4]-vi[5]; vr[4]+=vr[5]; vi[4]+=vi[5]; vr[5]=tr; vi[5]=ti;
    tr=vr[6]-vr[7]; ti=vi[6]-vi[7]; vr[6]+=vr[7]; vi[6]+=vi[7]; vr[7]=tr; vi[7]=ti;
}

template<int SIGN>
__device__ __forceinline__ void radix4_lanes(float (&zr)[8], float (&zi)[8], int lane) {
    const float E = (float)SIGN;
    float s16 = (lane & 16) ? -1.0f : 1.0f;
    float s8  = (lane & 8)  ? -1.0f : 1.0f;
    bool tw = ((lane & 24) == 24);
#pragma unroll
    for (int r = 0; r < 8; r++) {
        float pr = __shfl_xor_sync(0xffffffffu, zr[r], 16);
        float pi = __shfl_xor_sync(0xffffffffu, zi[r], 16);
        float ar = fmaf(s16, zr[r], pr);
        float ai = fmaf(s16, zi[r], pi);
        if (tw) { float tt = ar; ar = -E * ai; ai = E * tt; }
        float qr = __shfl_xor_sync(0xffffffffu, ar, 8);
        float qi = __shfl_xor_sync(0xffffffffu, ai, 8);
        zr[r] = fmaf(s8, ar, qr);
        zi[r] = fmaf(s8, ai, qi);
    }
}

__device__ __constant__ int BRC[8] = {0, 4, 2, 6, 1, 5, 3, 7};

#define FFT256(SIGN, NEGI, vr, vi, SADDR_R, SADDR_W, t1r, t1i, t2r, t2i)           \
    {                                                                              \
        radix8<SIGN>(vr, vi);                                                      \
        _Pragma("unroll")                                                          \
        for (int j = 0; j < 8; j++) {                                              \
            int c = BRC[j];                                                        \
            float wr = t1r[c * 32 + lane];                                         \
            float wi = (NEGI) ? -t1i[c * 32 + lane] : t1i[c * 32 + lane];          \
            float nr = vr[j] * wr - vi[j] * wi;                                    \
            float ni = vr[j] * wi + vi[j] * wr;                                    \
            int row = lane + 32 * c;                                               \
            SADDR_W(row, nr, ni);                                                  \
        }                                                                          \
        __syncwarp();                                                              \
        _Pragma("unroll")                                                          \
        for (int r = 0; r < 8; r++) {                                              \
            int row = r + 8 * (lane >> 3) + 32 * (lane & 7);                       \
            SADDR_R(row, vr[r], vi[r]);                                            \
        }                                                                          \
        radix4_lanes<SIGN>(vr, vi, lane);                                          \
        _Pragma("unroll")                                                          \
        for (int r = 0; r < 8; r++) {                                              \
            float wr = t2r[r * 32 + lane];                                         \
            float wi = (NEGI) ? -t2i[r * 32 + lane] : t2i[r * 32 + lane];          \
            float nr = vr[r] * wr - vi[r] * wi;                                    \
            float ni = vr[r] * wi + vi[r] * wr;                                    \
            vr[r] = nr; vi[r] = ni;                                                \
        }                                                                          \
        radix8<SIGN>(vr, vi);                                                      \
    }

// ------- row forward FFT (pure; batch offset for stream split) -------
__global__ void k_row_fwd(const float* __restrict__ x, float* __restrict__ fftreg,
                          int bofs) {
    __shared__ float scr[8][512];
    __shared__ float t1r[256], t1i[256], t2r[256], t2i[256];
    int t = threadIdx.x, lane = t & 31, wp = t >> 5;
    t1r[t] = g_t1r_f[t]; t1i[t] = g_t1i_f[t];
    t2r[t] = g_t2r_f[t]; t2i[t] = g_t2i_f[t];
    __syncthreads();
    int row = blockIdx.x * 8 + wp, b = blockIdx.y + bofs;
    const float* xp = x + (size_t)b * HWSZ + (size_t)row * WW;
    float* sc = scr[wp];
    float vr[8], vi[8];
#pragma unroll
    for (int j = 0; j < 8; j++) { vr[j] = xp[lane + 32 * j]; vi[j] = 0.0f; }
#define RW_W(rw, nr, ni) { sc[SWZ(rw)] = nr; sc[256 + SWZ(rw)] = ni; }
#define RW_R(rw, or_, oi_) { or_ = sc[SWZ(rw)]; oi_ = sc[256 + SWZ(rw)]; }
    FFT256(-1, 0, vr, vi, RW_R, RW_W, t1r, t1i, t2r, t2i);
    int d0l = ((lane >> 4) & 1) + (((lane >> 3) & 1) << 1);
    float* fr = fftreg + (size_t)b * 2 * HWSZ + (size_t)row * WW;
    float* fi = fr + HWSZ;
#pragma unroll
    for (int j = 0; j < 8; j++) {
        int n = (lane & 7) + 8 * d0l + 32 * BRC[j];
        fr[n] = vr[j]; fi[n] = vi[j];
    }
#undef RW_W
#undef RW_R
}

// ---------- fused column kernel: 8-col tile, 256 threads, 5 CTAs/SM ----------
// per-column XOR in bit 4; bank-verified for all phases (see analysis)
#define CCP 256
#define SMADDR(col, row) ((col) * CCP + (SWZ(row) ^ ((((col) >> 2) & 1) << 4)))

__global__ void __launch_bounds__(256, 5)
k_col(float* __restrict__ fftreg, float* __restrict__ maskreg,
      float* __restrict__ ukreg, float* __restrict__ stage,
      unsigned sk0, unsigned sk1, int bofs) {
    extern __shared__ float sm[];
    float* sre = sm;                  // 8*256
    float* sim = sm + 8 * CCP;
    float* tw = sm + 16 * CCP;
    float* t1r_f = tw;        float* t1i_f = tw + 256;
    float* t2r_f = tw + 512;  float* t2i_f = tw + 768;
    int t = threadIdx.x, lane = t & 31, wp = t >> 5;   // wp 0..7 = column
    int b = blockIdx.y + bofs, c0 = blockIdx.x * 8;
    int cg = t & 1, rloc = t >> 1;                     // rloc 0..127
    float* fr = fftreg + (size_t)b * 2 * HWSZ;
    float* fi = fr + HWSZ;

    t1r_f[t] = g_t1r_f[t]; t1i_f[t] = g_t1i_f[t];
    t2r_f[t] = g_t2r_f[t]; t2i_f[t] = g_t2i_f[t];

    // load 256x8 tile (float4 gmem, 32B sector-aligned per row segment)
#pragma unroll
    for (int k = 0; k < 2; k++) {
        int row = k * 128 + rloc;
        int g = row * WW + c0 + cg * 4;
        float4 vre = *reinterpret_cast<const float4*>(fr + g);
        float4 vim = *reinterpret_cast<const float4*>(fi + g);
        int c = cg * 4;
        sre[SMADDR(c, row)] = vre.x;     sim[SMADDR(c, row)] = vim.x;
        sre[SMADDR(c + 1, row)] = vre.y; sim[SMADDR(c + 1, row)] = vim.y;
        sre[SMADDR(c + 2, row)] = vre.z; sim[SMADDR(c + 2, row)] = vim.z;
        sre[SMADDR(c + 3, row)] = vre.w; sim[SMADDR(c + 3, row)] = vim.w;
    }
    __syncthreads();

#define CW_W(rw, nr, ni) { sre[SMADDR(cc, rw)] = nr; sim[SMADDR(cc, rw)] = ni; }
#define CW_R(rw, or_, oi_) { or_ = sre[SMADDR(cc, rw)]; oi_ = sim[SMADDR(cc, rw)]; }
    int d0l = ((lane >> 4) & 1) + (((lane >> 3) & 1) << 1);
    // forward FFT: 1 column per warp
    {
        int cc = wp;
        float vr[8], vi[8];
#pragma unroll
        for (int j = 0; j < 8; j++) {
            int row = lane + 32 * j;
            vr[j] = sre[SMADDR(cc, row)]; vi[j] = sim[SMADDR(cc, row)];
        }
        FFT256(-1, 0, vr, vi, CW_R, CW_W, t1r_f, t1i_f, t2r_f, t2i_f);
        __syncwarp();
#pragma unroll
        for (int j = 0; j < 8; j++) {
            int row = (lane & 7) + 8 * d0l + 32 * BRC[j];
            sre[SMADDR(cc, row)] = vr[j]; sim[SMADDR(cc, row)] = vi[j];
        }
    }
    __syncthreads();

    // outputs: fft, mask (threefry), u_k; stash u_k in smem
    float* ur = ukreg + (size_t)b * 2 * HWSZ;
    float* ui = ur + HWSZ;
    float* mk = maskreg + (size_t)b * HWSZ;
    float rr = g_r, bb2 = g_beta;
    int le = g_le;
#pragma unroll 1
    for (int k = 0; k < 2; k++) {
        int row = k * 128 + rloc;
        int g = row * WW + c0 + cg * 4;
        int c = cg * 4;
        float mm[4];
        float4 p1 = *reinterpret_cast<const float4*>(g_prob2 + g);
        float pv[4] = {p1.x, p1.y, p1.z, p1.w};
        unsigned base = (unsigned)(b * HWSZ + g);
#pragma unroll
        for (int q = 0; q < 4; q++) {
            float p2 = le ? __fmul_rn(pv[q], rr)
                          : __fsub_rn(1.0f, __fmul_rn(__fsub_rn(1.0f, pv[q]), bb2));
            unsigned o0, o1;
            threefry2x32(sk0, sk1, 0u, base + (unsigned)q, o0, o1);
            unsigned bits = o0 ^ o1;
            float u = __uint_as_float((bits >> 9) | 0x3f800000u) - 1.0f;
            mm[q] = (p2 > u) ? 1.0f : 0.0f;
        }
        *reinterpret_cast<float4*>(mk + g) = make_float4(mm[0], mm[1], mm[2], mm[3]);
        float xr[4], xi[4], kr[4], ki[4];
#pragma unroll
        for (int q = 0; q < 4; q++) {
            xr[q] = sre[SMADDR(c + q, row)];
            xi[q] = sim[SMADDR(c + q, row)];
            kr[q] = xr[q] * mm[q]; ki[q] = xi[q] * mm[q];
            sre[SMADDR(c + q, row)] = kr[q];
            sim[SMADDR(c + q, row)] = ki[q];
        }
        *reinterpret_cast<float4*>(fr + g) = make_float4(xr[0], xr[1], xr[2], xr[3]);
        *reinterpret_cast<float4*>(fi + g) = make_float4(xi[0], xi[1], xi[2], xi[3]);
        *reinterpret_cast<float4*>(ur + g) = make_float4(kr[0], kr[1], kr[2], kr[3]);
        *reinterpret_cast<float4*>(ui + g) = make_float4(ki[0], ki[1], ki[2], ki[3]);
    }
    __syncthreads();

    // inverse FFT: 1 column per warp (conjugate twiddles via NEGI), scale 1/256
    {
        int cc = wp;
        float vr[8], vi[8];
#pragma unroll
        for (int j = 0; j < 8; j++) {
            int row = lane + 32 * j;
            vr[j] = sre[SMADDR(cc, row)]; vi[j] = sim[SMADDR(cc, row)];
        }
        FFT256(1, 1, vr, vi, CW_R, CW_W, t1r_f, t1i_f, t2r_f, t2i_f);
        __syncwarp();
        const float sc = 1.0f / 256.0f;
#pragma unroll
        for (int j = 0; j < 8; j++) {
            int row = (lane & 7) + 8 * d0l + 32 * BRC[j];
            sre[SMADDR(cc, row)] = vr[j] * sc; sim[SMADDR(cc, row)] = vi[j] * sc;
        }
    }
    __syncthreads();
#undef CW_W
#undef CW_R

    // store to staging (uifft region)
    float* dr = stage + (size_t)b * 2 * HWSZ;
    float* di = dr + HWSZ;
#pragma unroll
    for (int k = 0; k < 2; k++) {
        int row = k * 128 + rloc;
        int g = row * WW + c0 + cg * 4;
        int c = cg * 4;
        float4 vre, vim;
        vre.x = sre[SMADDR(c, row)];     vim.x = sim[SMADDR(c, row)];
        vre.y = sre[SMADDR(c + 1, row)]; vim.y = sim[SMADDR(c + 1, row)];
        vre.z = sre[SMADDR(c + 2, row)]; vim.z = sim[SMADDR(c + 2, row)];
        vre.w = sre[SMADDR(c + 3, row)]; vim.w = sim[SMADDR(c + 3, row)];
        *reinterpret_cast<float4*>(dr + g) = vre;
        *reinterpret_cast<float4*>(di + g) = vim;
    }
}

// ---------- row inverse FFT (in place on uifft) + complex abs ----------
__global__ void k_row_inv(float* __restrict__ uifft, float* __restrict__ cabs,
                          int bofs) {
    __shared__ float scr[8][512];
    __shared__ float t1r[256], t1i[256], t2r[256], t2i[256];
    int t = threadIdx.x, lane = t & 31, wp = t >> 5;
    t1r[t] = g_t1r_i[t]; t1i[t] = g_t1i_i[t];
    t2r[t] = g_t2r_i[t]; t2i[t] = g_t2i_i[t];
    __syncthreads();
    int row = blockIdx.x * 8 + wp, b = blockIdx.y + bofs;
    float* fr = uifft + (size_t)b * 2 * HWSZ + (size_t)row * WW;
    float* fi = fr + HWSZ;
    float* sc = scr[wp];
    float vr[8], vi[8];
#pragma unroll
    for (int j = 0; j < 8; j++) { vr[j] = fr[lane + 32 * j]; vi[j] = fi[lane + 32 * j]; }
#define RW_W(rw, nr, ni) { sc[SWZ(rw)] = nr; sc[256 + SWZ(rw)] = ni; }
#define RW_R(rw, or_, oi_) { or_ = sc[SWZ(rw)]; oi_ = sc[256 + SWZ(rw)]; }
    FFT256(1, 0, vr, vi, RW_R, RW_W, t1r, t1i, t2r, t2i);
    int d0l = ((lane >> 4) & 1) + (((lane >> 3) & 1) << 1);
    float* ap = cabs + (size_t)b * HWSZ + (size_t)row * WW;
#pragma unroll
    for (int j = 0; j < 8; j++) {
        int n = (lane & 7) + 8 * d0l + 32 * BRC[j];
        fr[n] = vr[j]; fi[n] = vi[j];
        ap[n] = sqrtf(vr[j] * vr[j] + vi[j] * vi[j]);
    }
#undef RW_W
#undef RW_R
}

extern "C" void kernel_launch(void* const* d_in, const int* in_sizes, int n_in,
                              void* d_out, int out_size) {
    const float* x = (const float*)d_in[0];
    const float* w = (const float*)d_in[1];
    if (n_in >= 2 && in_sizes[0] == HWSZ) {
        x = (const float*)d_in[1];
        w = (const float*)d_in[0];
    }
    float* out   = (float*)d_out;
    float* uifft = out + OFF_UIFFT;
    float* cabs  = out + OFF_ABS;
    float* mask  = out + OFF_MASK;
    float* fft   = out + OFF_FFT;
    float* uk    = out + OFF_UK;

    unsigned sk0, sk1;
    threefry2x32(0u, 42u, 0u, 1u, sk0, sk1);

    const int col_smem = (2 * 8 * CCP + 4 * 256) * (int)sizeof(float);   // 20480
    const int HB = BB / 2;

    static cudaStream_t s1 = 0, s2 = 0;
    static cudaEvent_t ev_fork = 0, ev_final = 0, ev_end = 0;
    static int inited = 0;
    if (!inited) {
        cudaStreamCreateWithFlags(&s1, cudaStreamNonBlocking);
        cudaStreamCreateWithFlags(&s2, cudaStreamNonBlocking);
        cudaEventCreateWithFlags(&ev_fork, cudaEventDisableTiming);
        cudaEventCreateWithFlags(&ev_final, cudaEventDisableTiming);
        cudaEventCreateWithFlags(&ev_end, cudaEventDisableTiming);
        cudaFuncSetAttribute(k_col, cudaFuncAttributeMaxDynamicSharedMemorySize, col_smem);
        inited = 1;
    }

    cudaEventRecord(ev_fork, 0);
    cudaStreamWaitEvent(s1, ev_fork, 0);
    cudaStreamWaitEvent(s2, ev_fork, 0);
    k_reduce<<<64, 256, 0, s1>>>(w);
    k_final<<<1, 256, 0, s1>>>();
    cudaEventRecord(ev_final, s1);

    k_row_fwd<<<dim3(HH / 8, HB), 256>>>(x, fft, 0);
    k_row_fwd<<<dim3(HH / 8, HB), 256, 0, s2>>>(x, fft, HB);

    cudaStreamWaitEvent(0, ev_final, 0);
    cudaStreamWaitEvent(s2, ev_final, 0);

    k_col<<<dim3(WW / 8, HB), 256, col_smem>>>(fft, mask, uk, uifft, sk0, sk1, 0);
    k_col<<<dim3(WW / 8, HB), 256, col_smem, s2>>>(fft, mask, uk, uifft, sk0, sk1, HB);

    k_row_inv<<<dim3(HH / 8, HB), 256>>>(uifft, cabs, 0);
    k_row_inv<<<dim3(HH / 8, HB), 256, 0, s2>>>(uifft, cabs, HB);

    cudaEventRecord(ev_end, s2);
    cudaStreamWaitEvent(0, ev_end, 0);
}